// round 1
// baseline (speedup 1.0000x reference)
#include <cuda_runtime.h>
#include <cstdint>

// Problem shape (fixed per reference setup_inputs):
//   x: (128, 1, 28, 28) f32  -> out: (128, 785, 28, 28) f32
// out[b,0,h,w]       = new_pv(x[b,0,h,w])
// out[b,1+i,h,w]     = (h*28+w == i) ? new_e(x flat i) : 0
static constexpr int B   = 128;
static constexpr int HW  = 784;            // 28*28
static constexpr int CPB = 785 * 784;      // floats per batch = 615,440
static constexpr long long TOTAL = (long long)B * CPB;  // 78,776,320 floats

// ---------------------------------------------------------------------------
// Kernel 1: zero the whole output with 16B stores. TOTAL % 4 == 0.
// ---------------------------------------------------------------------------
__global__ void zero_fill_kernel(float4* __restrict__ out, long long n4) {
    long long idx = (long long)blockIdx.x * blockDim.x + threadIdx.x;
    if (idx < n4) {
        out[idx] = make_float4(0.f, 0.f, 0.f, 0.f);
    }
}

// ---------------------------------------------------------------------------
// Kernel 2: compute new_pv / new_e and scatter the non-zero elements.
// One thread per (b, i), i in [0, 784).
// ---------------------------------------------------------------------------
__global__ void scatter_kernel(const float* __restrict__ x,
                               float* __restrict__ out) {
    int idx = blockIdx.x * blockDim.x + threadIdx.x;   // b*HW + i
    if (idx >= B * HW) return;

    int b = idx / HW;
    int i = idx - b * HW;

    const float eps = 0.1f;
    float pv = x[idx];

    bool low  = pv < eps;
    bool high = pv > 1.0f - eps;

    float new_pv = low  ? (pv + eps) * 0.5f
                 : high ? (pv + (1.0f - eps)) * 0.5f
                 :        pv;
    float new_e  = low  ? (eps + pv) * 0.5f
                 : high ? ((1.0f - pv) + eps) * 0.5f
                 :        eps;

    long long base = (long long)b * CPB;
    out[base + i] = new_pv;                              // channel 0
    out[base + (long long)(1 + i) * HW + i] = new_e;     // diagonal of channel 1+i
}

extern "C" void kernel_launch(void* const* d_in, const int* in_sizes, int n_in,
                              void* d_out, int out_size) {
    const float* x = (const float*)d_in[0];
    float* out = (float*)d_out;

    // Zero fill: TOTAL/4 float4 stores.
    long long n4 = TOTAL / 4;                 // 19,694,080
    int threads = 256;
    long long blocks = (n4 + threads - 1) / threads;
    zero_fill_kernel<<<(unsigned)blocks, threads>>>((float4*)out, n4);

    // Scatter the non-zeros (ordered after fill by stream order).
    int n = B * HW;                           // 100,352
    int sblocks = (n + threads - 1) / threads;
    scatter_kernel<<<sblocks, threads>>>(x, out);
}

// round 2
// speedup vs baseline: 1.0058x; 1.0058x over previous
#include <cuda_runtime.h>
#include <cstdint>

// x: (128, 1, 28, 28) f32  -> out: (128, 785, 28, 28) f32
// out[b,0,:]   = new_pv(x[b])
// out[b,1+i,:] = new_e(x[b,i]) at flat pos i, else 0
static constexpr unsigned B    = 128;
static constexpr unsigned HW   = 784;              // 28*28
static constexpr unsigned CPB  = 785u * 784u;      // floats per batch = 615,440
static constexpr unsigned CPB4 = CPB / 4u;         // 153,860 float4 per batch
static constexpr unsigned N4   = B * CPB4;         // 19,694,080 float4 total

__device__ __forceinline__ float pv_map(float pv) {
    const float eps = 0.1f;
    bool low  = pv < eps;
    bool high = pv > 1.0f - eps;
    return low  ? (pv + eps) * 0.5f
         : high ? (pv + (1.0f - eps)) * 0.5f
         :        pv;
}

__device__ __forceinline__ float e_map(float pv) {
    const float eps = 0.1f;
    bool low  = pv < eps;
    bool high = pv > 1.0f - eps;
    return low  ? (eps + pv) * 0.5f
         : high ? ((1.0f - pv) + eps) * 0.5f
         :        eps;
}

// One thread = one output float4. Fully fused: zeros + channel0 + diagonal.
__global__ void fused_kernel(const float* __restrict__ x,
                             float4* __restrict__ out) {
    unsigned idx = blockIdx.x * blockDim.x + threadIdx.x;
    if (idx >= N4) return;

    unsigned b  = idx / CPB4;
    unsigned j4 = idx - b * CPB4;        // float4 index within batch

    float4 v = make_float4(0.f, 0.f, 0.f, 0.f);

    if (j4 < HW / 4u) {
        // Channel 0: contiguous pv map of 4 input values.
        const float4 xv = reinterpret_cast<const float4*>(x)[b * (HW / 4u) + j4];
        v.x = pv_map(xv.x);
        v.y = pv_map(xv.y);
        v.z = pv_map(xv.z);
        v.w = pv_map(xv.w);
    } else {
        // Channels 1..784: zero except the single diagonal element.
        unsigned j = j4 * 4u;            // float offset within batch (>= 784)
        unsigned c = j / HW;             // channel (>= 1); HW divides 4-chunks cleanly
        unsigned r = j - c * HW;         // offset within channel (multiple of 4)
        unsigned i = c - 1u;             // diagonal position for this channel
        if (i >= r && i < r + 4u) {
            float pv = x[b * HW + i];
            reinterpret_cast<float*>(&v)[i - r] = e_map(pv);
        }
    }

    out[idx] = v;
}

extern "C" void kernel_launch(void* const* d_in, const int* in_sizes, int n_in,
                              void* d_out, int out_size) {
    const float* x = (const float*)d_in[0];
    float4* out = (float4*)d_out;

    const int threads = 256;
    const unsigned blocks = (N4 + threads - 1) / threads;
    fused_kernel<<<blocks, threads>>>(x, out);
}